// round 12
// baseline (speedup 1.0000x reference)
#include <cuda_runtime.h>
#include <cstdint>

// out[b, f, s] = x[b, 0, s] * w[f, s] + bias[f, s]
// B=128, F=256, S=4096. HBM-write-bound: 512 MiB out.
//
// R12: store-path experiment. Compute each (b,f) output row (16 KB) into a
// double-buffered smem staging area, then issue ONE cp.async.bulk (DMA) store
// of 16 KB contiguous per row. The DRAM controller sees long monotone write
// trains (32768 x 16 KB) instead of 512 B STG granules at 16 KB strides.
// Proven invariants kept: zero in-loop global loads (x staged in smem,
// w/bias full rows in regs). FT=2, BT=4, 96 KB smem, 2 CTAs/SM.

#define S4     1024        // float4 per row (4096 floats = 16 KB)
#define NFILT  256
#define BATCH  128
#define FT     2           // filters per CTA (full w/bias rows in regs)
#define BT     4           // batches per CTA (full x rows in smem)
#define SMEM_BYTES ((BT * S4 + 2 * S4) * 16)   // 64 KB x-stage + 32 KB out-stage

__global__ __launch_bounds__(256, 2) void dense_filter_expand_kernel(
    const float4* __restrict__ x,     // [B, S4]
    const float4* __restrict__ w,     // [F, S4]
    const float4* __restrict__ bias,  // [F, S4]
    float4* __restrict__ out)         // [B, F, S4]
{
    extern __shared__ float4 sm[];
    float4* xsm  = sm;                 // BT * S4  (x rows)
    float4* obuf = sm + BT * S4;       // 2 * S4   (double-buffered out row)

    const int t  = threadIdx.x;        // 0..255
    const int fg = blockIdx.x;         // 0..127
    const int bg = blockIdx.y;         // 0..31
    const int f0 = fg * FT;
    const int b0 = bg * BT;

    // Preamble: stage full x rows for BT batches (16 independent LDGs).
#pragma unroll
    for (int i = 0; i < BT; i++)
#pragma unroll
        for (int c = 0; c < 4; c++)
            xsm[i * S4 + c * 256 + t] = __ldg(&x[(size_t)(b0 + i) * S4 + c * 256 + t]);

    // Register-cache full w/bias rows for FT filters (64 regs).
    float4 wv[FT][4], bv[FT][4];
#pragma unroll
    for (int ff = 0; ff < FT; ff++)
#pragma unroll
        for (int c = 0; c < 4; c++) {
            wv[ff][c] = __ldg(&w[(size_t)(f0 + ff) * S4 + c * 256 + t]);
            bv[ff][c] = __ldg(&bias[(size_t)(f0 + ff) * S4 + c * 256 + t]);
        }
    __syncthreads();

    const uint32_t obuf_base = (uint32_t)__cvta_generic_to_shared(obuf);

    // Steady state: compose one 16 KB (b,f) row in smem, DMA it out.
#pragma unroll 1
    for (int it = 0; it < BT * FT; it++) {
        const int bb   = it >> 1;      // batch index within tile
        const int ff   = it & 1;       // filter index within tile
        const int slot = it & 1;       // staging buffer

        // Buffer reuse: the bulk store issued 2 iterations ago used this slot.
        if (t == 0 && it >= 2)
            asm volatile("cp.async.bulk.wait_group.read 1;" ::: "memory");
        __syncthreads();

        float4* ob = obuf + slot * S4;
#pragma unroll
        for (int c = 0; c < 4; c++) {
            const float4 xv = xsm[bb * S4 + c * 256 + t];
            float4 o;
            o.x = fmaf(xv.x, wv[ff][c].x, bv[ff][c].x);
            o.y = fmaf(xv.y, wv[ff][c].y, bv[ff][c].y);
            o.z = fmaf(xv.z, wv[ff][c].z, bv[ff][c].z);
            o.w = fmaf(xv.w, wv[ff][c].w, bv[ff][c].w);
            ob[c * 256 + t] = o;
        }
        // Make generic-proxy STS visible to the async proxy, then sync.
        asm volatile("fence.proxy.async.shared::cta;" ::: "memory");
        __syncthreads();

        if (t == 0) {
            float4* dst = out + ((size_t)(b0 + bb) * NFILT + (f0 + ff)) * S4;
            uint32_t src = obuf_base + (uint32_t)(slot * S4 * 16);
            unsigned bytes = S4 * 16;  // 16384
            asm volatile(
                "cp.async.bulk.global.shared::cta.bulk_group [%0], [%1], %2;"
                :: "l"(dst), "r"(src), "r"(bytes) : "memory");
            asm volatile("cp.async.bulk.commit_group;" ::: "memory");
        }
    }

    // Drain all outstanding bulk stores before exit.
    if (t == 0)
        asm volatile("cp.async.bulk.wait_group 0;" ::: "memory");
}

extern "C" void kernel_launch(void* const* d_in, const int* in_sizes, int n_in,
                              void* d_out, int out_size) {
    const float4* x    = (const float4*)d_in[0];   // inputs [128,1,4096]
    const float4* w    = (const float4*)d_in[1];   // w [256,4096]
    const float4* bias = (const float4*)d_in[2];   // b [256,4096]
    float4* out = (float4*)d_out;

    // CPU-side attribute set (not a stream op; graph-capture safe, no alloc).
    cudaFuncSetAttribute(dense_filter_expand_kernel,
                         cudaFuncAttributeMaxDynamicSharedMemorySize, SMEM_BYTES);

    dim3 grid(NFILT / FT, BATCH / BT);             // (128, 32) = 4096
    dense_filter_expand_kernel<<<grid, 256, SMEM_BYTES>>>(x, w, bias, out);
}

// round 13
// speedup vs baseline: 2.2197x; 2.2197x over previous
#include <cuda_runtime.h>

// out[b, f, s] = x[b, 0, s] * w[f, s] + bias[f, s]
// B=128, F=256, S=4096. HBM-write-bound: 512 MiB out.
//
// R13: winning structure (zero in-loop global loads, __stcs) with maximal
// store-burst length. Each CTA: FT=2 FULL filter rows in regs (64 regs),
// BT=4 full x rows in 64 KB smem. Per batch it writes 2 adjacent 16 KB
// filter rows = 32 KB monotone contiguous (R10 bursts were 4 KB at 16 KB
// stride). Plain STG path — no syncs, no DMA (R12's failure mode).

#define S4     1024        // float4 per row (4096 floats = 16 KB)
#define NFILT  256
#define BATCH  128
#define FT     2           // filters per CTA (full rows register-cached)
#define BT     4           // batches per CTA (full rows in smem)
#define SMEM_BYTES (BT * S4 * 16)   // 64 KB

__global__ __launch_bounds__(256, 2) void dense_filter_expand_kernel(
    const float4* __restrict__ x,     // [B, S4]
    const float4* __restrict__ w,     // [F, S4]
    const float4* __restrict__ bias,  // [F, S4]
    float4* __restrict__ out)         // [B, F, S4]
{
    extern __shared__ float4 xsm[];            // BT * S4

    const int t  = threadIdx.x;                // 0..255
    const int fg = blockIdx.x;                 // 0..127 filter pair
    const int bg = blockIdx.y;                 // 0..31  batch group
    const int f0 = fg * FT;
    const int b0 = bg * BT;

    // Preamble: stage BT full x rows into smem (16 independent LDGs).
#pragma unroll
    for (int i = 0; i < BT; i++)
#pragma unroll
        for (int c = 0; c < 4; c++)
            xsm[i * S4 + c * 256 + t] =
                __ldg(&x[(size_t)(b0 + i) * S4 + c * 256 + t]);

    // Register-cache FULL w/bias rows for 2 filters (16 float4 = 64 regs).
    float4 wv[FT][4], bv[FT][4];
#pragma unroll
    for (int ff = 0; ff < FT; ff++)
#pragma unroll
        for (int c = 0; c < 4; c++) {
            wv[ff][c] = __ldg(&w[(size_t)(f0 + ff) * S4 + c * 256 + t]);
            bv[ff][c] = __ldg(&bias[(size_t)(f0 + ff) * S4 + c * 256 + t]);
        }
    __syncthreads();

    // Steady state: per batch, write 2 adjacent 16 KB rows = 32 KB monotone.
#pragma unroll 1
    for (int bb = 0; bb < BT; bb++) {
        float4* obase = out + ((size_t)(b0 + bb) * NFILT + f0) * S4;

#pragma unroll
        for (int ff = 0; ff < FT; ff++) {
            float4* orow = obase + (size_t)ff * S4;
#pragma unroll
            for (int c = 0; c < 4; c++) {
                const float4 xv = xsm[bb * S4 + c * 256 + t];
                float4 o;
                o.x = fmaf(xv.x, wv[ff][c].x, bv[ff][c].x);
                o.y = fmaf(xv.y, wv[ff][c].y, bv[ff][c].y);
                o.z = fmaf(xv.z, wv[ff][c].z, bv[ff][c].z);
                o.w = fmaf(xv.w, wv[ff][c].w, bv[ff][c].w);
                // Streaming store: output is write-once, never re-read.
                __stcs(&orow[c * 256 + t], o);
            }
        }
    }
}

extern "C" void kernel_launch(void* const* d_in, const int* in_sizes, int n_in,
                              void* d_out, int out_size) {
    const float4* x    = (const float4*)d_in[0];   // inputs [128,1,4096]
    const float4* w    = (const float4*)d_in[1];   // w [256,4096]
    const float4* bias = (const float4*)d_in[2];   // b [256,4096]
    float4* out = (float4*)d_out;

    // CPU-side attribute set (not a stream op; graph-capture safe, no alloc).
    cudaFuncSetAttribute(dense_filter_expand_kernel,
                         cudaFuncAttributeMaxDynamicSharedMemorySize, SMEM_BYTES);

    dim3 grid(NFILT / FT, BATCH / BT);             // (128, 32) = 4096
    dense_filter_expand_kernel<<<grid, 256, SMEM_BYTES>>>(x, w, bias, out);
}

// round 14
// speedup vs baseline: 2.4137x; 1.0874x over previous
#include <cuda_runtime.h>

// out[b, f, s] = x[b, 0, s] * w[f, s] + bias[f, s]
// B=128, F=256, S=4096. HBM-write-bound: 512 MiB out.
//
// R14: R10 winning structure (x staged in smem, w/bias reg-cached,
// filter-inner 16KB-stride __stcs bursts, zero in-loop global loads) pushed
// to 6 CTAs/SM: FT=2 (16-reg w/bias cache), BT=8 (32 KB smem),
// __launch_bounds__(256,6) => ~42-reg budget, occ ~69%, 888 concurrent CTAs.
// Occupancy sweep step 3 (23% -> 46% -> 69%).

#define S4     1024        // float4 per row (4096 floats)
#define NFILT  256
#define BATCH  128
#define FT     2           // filters per block (w/bias register-cached)
#define BT     8           // batches per block (x staged in smem)
#define CHUNK4 256         // float4 per s-chunk, one per thread

__global__ __launch_bounds__(256, 6) void dense_filter_expand_kernel(
    const float4* __restrict__ x,     // [B, S4]
    const float4* __restrict__ w,     // [F, S4]
    const float4* __restrict__ bias,  // [F, S4]
    float4* __restrict__ out)         // [B, F, S4]
{
    __shared__ float4 xs[BT * CHUNK4];         // 32 KB

    const int t  = threadIdx.x;                // 0..255
    const int sc = blockIdx.x;                 // 0..3    s-chunk
    const int fg = blockIdx.y;                 // 0..127  filter group
    const int bg = blockIdx.z;                 // 0..15   batch group
    const int s4 = sc * CHUNK4 + t;            // float4 index within a row
    const int b0 = bg * BT;
    const int f0 = fg * FT;

    // Preamble: stage x chunks for 8 batches into smem (independent LDGs).
#pragma unroll
    for (int i = 0; i < BT; i++)
        xs[i * CHUNK4 + t] = __ldg(&x[(size_t)(b0 + i) * S4 + s4]);

    // Register-cache w/bias chunks for the 2 filters (16 regs).
    float4 wv[FT], bv[FT];
#pragma unroll
    for (int ff = 0; ff < FT; ff++) {
        wv[ff] = __ldg(&w[(size_t)(f0 + ff) * S4 + s4]);
        bv[ff] = __ldg(&bias[(size_t)(f0 + ff) * S4 + s4]);
    }
    __syncthreads();

    // Steady state: 1 LDS + 2 streaming stores per batch. Zero global loads.
#pragma unroll 1
    for (int bb = 0; bb < BT; bb++) {
        const float4 xv = xs[bb * CHUNK4 + t];

        float4* obase = out + ((size_t)(b0 + bb) * NFILT + f0) * S4 + s4;
#pragma unroll
        for (int ff = 0; ff < FT; ff++) {
            float4 o;
            o.x = fmaf(xv.x, wv[ff].x, bv[ff].x);
            o.y = fmaf(xv.y, wv[ff].y, bv[ff].y);
            o.z = fmaf(xv.z, wv[ff].z, bv[ff].z);
            o.w = fmaf(xv.w, wv[ff].w, bv[ff].w);
            // Streaming store: output is write-once, never re-read.
            __stcs(obase + (size_t)ff * S4, o);
        }
    }
}

extern "C" void kernel_launch(void* const* d_in, const int* in_sizes, int n_in,
                              void* d_out, int out_size) {
    const float4* x    = (const float4*)d_in[0];   // inputs [128,1,4096]
    const float4* w    = (const float4*)d_in[1];   // w [256,4096]
    const float4* bias = (const float4*)d_in[2];   // b [256,4096]
    float4* out = (float4*)d_out;

    dim3 grid(S4 / CHUNK4, NFILT / FT, BATCH / BT);  // (4, 128, 16) = 8192
    dense_filter_expand_kernel<<<grid, 256>>>(x, w, bias, out);
}